// round 1
// baseline (speedup 1.0000x reference)
#include <cuda_runtime.h>

#define B_  4
#define S_  2048
#define D_  1024
#define H_  16
#define DK_ 64
#define M_  (B_*S_)    // 8192
#define N_  (H_*DK_)   // 1024
#define KD_ D_         // 1024
#define LDS 68         // padded smem stride (floats), keeps 16B alignment

// Scratch for projected q/k/v in [B,H,S,DK] layout (allocation-free rule: device globals)
__device__ float g_q[B_*H_*S_*DK_];
__device__ float g_k[B_*H_*S_*DK_];
__device__ float g_v[B_*H_*S_*DK_];

// ---------------------------------------------------------------------------
// Projection GEMM: out[b,h,s,d] = (X[m,:] @ W[:,n] + bias[n]) * scale
// X: [8192,1024] row-major, W: [1024,1024] row-major (out = X @ W).
// Tile: BM=128, BN=128, BK=16; 256 threads; 8x8 register tile.
// ---------------------------------------------------------------------------
__global__ __launch_bounds__(256) void proj_kernel(
    const float* __restrict__ X, const float* __restrict__ W,
    const float* __restrict__ bias, float* __restrict__ out, float scale)
{
    __shared__ float As[16][132];   // A tile transposed: As[k][m], padded
    __shared__ float Bs[16][128];   // B tile: Bs[k][n]

    const int tid = threadIdx.x;
    const int tx  = tid & 15;
    const int ty  = tid >> 4;
    const int bm  = blockIdx.y * 128;
    const int bn  = blockIdx.x * 128;

    float acc[8][8];
    #pragma unroll
    for (int i = 0; i < 8; i++)
        #pragma unroll
        for (int j = 0; j < 8; j++) acc[i][j] = 0.f;

    const int arow = tid >> 2;          // 0..63
    const int acol = (tid & 3) << 2;    // 0,4,8,12
    const int brow = tid >> 5;          // 0..7
    const int bcol = (tid & 31) << 2;   // 0..124

    for (int k0 = 0; k0 < KD_; k0 += 16) {
        #pragma unroll
        for (int r = 0; r < 2; r++) {
            int row = arow + r * 64;
            float4 a = *(const float4*)&X[(bm + row) * KD_ + k0 + acol];
            As[acol + 0][row] = a.x;
            As[acol + 1][row] = a.y;
            As[acol + 2][row] = a.z;
            As[acol + 3][row] = a.w;
        }
        #pragma unroll
        for (int r = 0; r < 2; r++) {
            int row = brow + r * 8;
            *(float4*)&Bs[row][bcol] = *(const float4*)&W[(k0 + row) * N_ + bn + bcol];
        }
        __syncthreads();

        #pragma unroll
        for (int k = 0; k < 16; k++) {
            float ra[8], rb[8];
            *(float4*)&ra[0] = *(float4*)&As[k][ty * 8];
            *(float4*)&ra[4] = *(float4*)&As[k][ty * 8 + 4];
            *(float4*)&rb[0] = *(float4*)&Bs[k][tx * 8];
            *(float4*)&rb[4] = *(float4*)&Bs[k][tx * 8 + 4];
            #pragma unroll
            for (int i = 0; i < 8; i++)
                #pragma unroll
                for (int j = 0; j < 8; j++)
                    acc[i][j] += ra[i] * rb[j];
        }
        __syncthreads();
    }

    // Epilogue: bias + scale, write to [B,H,S,DK]
    #pragma unroll
    for (int i = 0; i < 8; i++) {
        int m = bm + ty * 8 + i;
        int b = m >> 11;           // /S_
        int s = m & (S_ - 1);
        #pragma unroll
        for (int jj = 0; jj < 8; jj += 4) {
            int n = bn + tx * 8 + jj;
            int h = n >> 6;        // /DK_
            int d = n & 63;
            float4 o;
            o.x = (acc[i][jj + 0] + bias[n + 0]) * scale;
            o.y = (acc[i][jj + 1] + bias[n + 1]) * scale;
            o.z = (acc[i][jj + 2] + bias[n + 2]) * scale;
            o.w = (acc[i][jj + 3] + bias[n + 3]) * scale;
            *(float4*)&out[(((b * H_ + h) * S_) + s) * DK_ + d] = o;
        }
    }
}

// ---------------------------------------------------------------------------
// Attention: one block per (b,h, 64-query tile). Streams 64-key tiles.
// Single-pass (reference uses raw exp, no max-subtraction).
// smem: qT[64d][64q], kPT (union: kT[64d][64k] then P^T[64k][64q]), Vs[64k][64dv]
// ---------------------------------------------------------------------------
__global__ __launch_bounds__(256) void attn_kernel(
    const float* __restrict__ maskg, float* __restrict__ out)
{
    extern __shared__ float sm[];
    float* qT     = sm;                 // [64][LDS]
    float* kPT    = sm + 64 * LDS;      // [64][LDS]
    float* Vs     = sm + 2 * 64 * LDS;  // [64][LDS]
    float* mask_s = sm + 3 * 64 * LDS;  // [64]
    float* denom  = mask_s + 64;        // [64]

    const int tid = threadIdx.x;
    const int tx  = tid & 15;
    const int ty  = tid >> 4;
    const int bh  = blockIdx.y;
    const int b   = bh >> 4;
    const int h   = bh & 15;
    const int q0  = blockIdx.x * 64;

    const float* qg = g_q + ((size_t)bh * S_ + q0) * DK_;

    // Load q tile transposed: qT[d][q]
    #pragma unroll
    for (int it = 0; it < 4; it++) {
        int idx = tid + it * 256;        // 1024 float4s total
        int row = idx >> 4;              // q row 0..63
        int c   = (idx & 15) << 2;       // d 0..60
        float4 a = *(const float4*)&qg[row * DK_ + c];
        qT[(c + 0) * LDS + row] = a.x;
        qT[(c + 1) * LDS + row] = a.y;
        qT[(c + 2) * LDS + row] = a.z;
        qT[(c + 3) * LDS + row] = a.w;
    }
    if (tid < 64) denom[tid] = 0.f;

    float o_acc[4][4];
    #pragma unroll
    for (int i = 0; i < 4; i++)
        #pragma unroll
        for (int j = 0; j < 4; j++) o_acc[i][j] = 0.f;

    for (int kt = 0; kt < S_ / 64; kt++) {
        const int k0 = kt * 64;
        const float* kg = g_k + ((size_t)bh * S_ + k0) * DK_;
        const float* vg = g_v + ((size_t)bh * S_ + k0) * DK_;

        __syncthreads();   // prior stage-2 reads of kPT/Vs complete; qT visible (kt==0)

        #pragma unroll
        for (int it = 0; it < 4; it++) {
            int idx = tid + it * 256;
            int row = idx >> 4;
            int c   = (idx & 15) << 2;
            float4 a = *(const float4*)&kg[row * DK_ + c];
            kPT[(c + 0) * LDS + row] = a.x;
            kPT[(c + 1) * LDS + row] = a.y;
            kPT[(c + 2) * LDS + row] = a.z;
            kPT[(c + 3) * LDS + row] = a.w;
            *(float4*)&Vs[row * LDS + c] = *(const float4*)&vg[row * DK_ + c];
        }
        if (tid < 64) mask_s[tid] = maskg[b * S_ + k0 + tid];
        __syncthreads();

        // Stage 1: scores[4q][4k] = sum_d qT[d][q] * kT[d][k]  (q already has 1/8)
        float sreg[4][4];
        #pragma unroll
        for (int i = 0; i < 4; i++)
            #pragma unroll
            for (int j = 0; j < 4; j++) sreg[i][j] = 0.f;

        #pragma unroll 8
        for (int d = 0; d < 64; d++) {
            float qa[4], ka[4];
            *(float4*)qa = *(float4*)&qT[d * LDS + ty * 4];
            *(float4*)ka = *(float4*)&kPT[d * LDS + tx * 4];
            #pragma unroll
            for (int i = 0; i < 4; i++)
                #pragma unroll
                for (int j = 0; j < 4; j++)
                    sreg[i][j] += qa[i] * ka[j];
        }
        __syncthreads();   // done reading kT; safe to overwrite with P^T

        // exp * mask, write P^T[k][q], accumulate row sums
        float mk[4];
        #pragma unroll
        for (int j = 0; j < 4; j++) mk[j] = mask_s[tx * 4 + j];

        #pragma unroll
        for (int i = 0; i < 4; i++) {
            float r = 0.f;
            #pragma unroll
            for (int j = 0; j < 4; j++) {
                float p = __expf(sreg[i][j]) * mk[j];
                kPT[(tx * 4 + j) * LDS + ty * 4 + i] = p;
                r += p;
            }
            r += __shfl_xor_sync(0xffffffffu, r, 8);
            r += __shfl_xor_sync(0xffffffffu, r, 4);
            r += __shfl_xor_sync(0xffffffffu, r, 2);
            r += __shfl_xor_sync(0xffffffffu, r, 1);
            if (tx == 0) denom[ty * 4 + i] += r;
        }
        __syncthreads();   // P^T + denom visible

        // Stage 2: O[4q][4dv] += sum_k P^T[k][q] * V[k][dv]
        #pragma unroll 8
        for (int kk = 0; kk < 64; kk++) {
            float pa[4], va[4];
            *(float4*)pa = *(float4*)&kPT[kk * LDS + ty * 4];
            *(float4*)va = *(float4*)&Vs[kk * LDS + tx * 4];
            #pragma unroll
            for (int i = 0; i < 4; i++)
                #pragma unroll
                for (int j = 0; j < 4; j++)
                    o_acc[i][j] += pa[i] * va[j];
        }
    }
    __syncthreads();

    // Epilogue: divide by denom, write [B,S,H*DV]
    #pragma unroll
    for (int i = 0; i < 4; i++) {
        int q = q0 + ty * 4 + i;
        float inv = 1.f / (denom[ty * 4 + i] + 1e-8f);
        float4 o;
        o.x = o_acc[i][0] * inv;
        o.y = o_acc[i][1] * inv;
        o.z = o_acc[i][2] * inv;
        o.w = o_acc[i][3] * inv;
        *(float4*)&out[((size_t)(b * S_ + q)) * N_ + h * DK_ + tx * 4] = o;
    }
}

// ---------------------------------------------------------------------------
extern "C" void kernel_launch(void* const* d_in, const int* in_sizes, int n_in,
                              void* d_out, int out_size)
{
    const float* Q    = (const float*)d_in[0];
    const float* Kin  = (const float*)d_in[1];
    const float* Vin  = (const float*)d_in[2];
    const float* mask = (const float*)d_in[3];
    const float* Wq   = (const float*)d_in[4];
    const float* bq   = (const float*)d_in[5];
    const float* Wk   = (const float*)d_in[6];
    const float* bk   = (const float*)d_in[7];
    const float* Wv   = (const float*)d_in[8];
    const float* bv   = (const float*)d_in[9];
    float* out = (float*)d_out;

    float *dq, *dk, *dv;
    cudaGetSymbolAddress((void**)&dq, g_q);
    cudaGetSymbolAddress((void**)&dk, g_k);
    cudaGetSymbolAddress((void**)&dv, g_v);

    dim3 pg(N_ / 128, M_ / 128);   // (8, 64)
    proj_kernel<<<pg, 256>>>(Q,   Wq, bq, dq, 0.125f);  // fold 1/sqrt(DK) into q
    proj_kernel<<<pg, 256>>>(Kin, Wk, bk, dk, 1.0f);
    proj_kernel<<<pg, 256>>>(Vin, Wv, bv, dv, 1.0f);

    size_t smem = (size_t)(3 * 64 * LDS + 128) * sizeof(float);  // 52736 B
    cudaFuncSetAttribute(attn_kernel,
                         cudaFuncAttributeMaxDynamicSharedMemorySize, (int)smem);
    attn_kernel<<<dim3(S_ / 64, B_ * H_), 256, smem>>>(mask, out);
}

// round 3
// speedup vs baseline: 1.1845x; 1.1845x over previous
#include <cuda_runtime.h>
#include <cuda_bf16.h>
#include <cstdint>

#define B_  4
#define S_  2048
#define D_  1024
#define H_  16
#define DK_ 64
#define M_  (B_*S_)    // 8192
#define N_  (H_*DK_)   // 1024
#define KD_ D_         // 1024
#define LDS 68         // attn smem stride (floats)

// ---------------- device scratch (allocation-free rule: device globals) ----
__device__ float g_q[B_*H_*S_*DK_];
__device__ float g_k[B_*H_*S_*DK_];
__device__ float g_v[B_*H_*S_*DK_];
__device__ __nv_bfloat16 g_xhi[M_*KD_];
__device__ __nv_bfloat16 g_xlo[M_*KD_];
__device__ __nv_bfloat16 g_wThi[N_*KD_];   // W transposed: [n][k]
__device__ __nv_bfloat16 g_wTlo[N_*KD_];

// ---------------- fp32 -> bf16 hi/lo split kernels --------------------------
__global__ void split_kernel(const float* __restrict__ x,
                             __nv_bfloat16* __restrict__ hi,
                             __nv_bfloat16* __restrict__ lo, int n)
{
    int i = blockIdx.x * blockDim.x + threadIdx.x;
    if (i < n) {
        float v = x[i];
        __nv_bfloat16 h = __float2bfloat16(v);
        hi[i] = h;
        lo[i] = __float2bfloat16(v - __bfloat162float(h));
    }
}
// W [K][N] row-major -> transposed hi/lo [N][K]
__global__ void splitT_kernel(const float* __restrict__ w,
                              __nv_bfloat16* __restrict__ hiT,
                              __nv_bfloat16* __restrict__ loT)
{
    int idx = blockIdx.x * blockDim.x + threadIdx.x;   // = n*1024 + k
    if (idx < N_ * KD_) {
        int n = idx >> 10, k = idx & 1023;
        float v = w[k * N_ + n];
        __nv_bfloat16 h = __float2bfloat16(v);
        hiT[idx] = h;
        loT[idx] = __float2bfloat16(v - __bfloat162float(h));
    }
}

// ---------------- mma.sync bf16 helper --------------------------------------
__device__ __forceinline__ void mma_bf16(float* d,
                                         uint32_t a0, uint32_t a1, uint32_t a2, uint32_t a3,
                                         uint32_t b0, uint32_t b1)
{
    asm volatile(
        "mma.sync.aligned.m16n8k16.row.col.f32.bf16.bf16.f32 "
        "{%0,%1,%2,%3}, {%4,%5,%6,%7}, {%8,%9}, {%0,%1,%2,%3};"
        : "+f"(d[0]), "+f"(d[1]), "+f"(d[2]), "+f"(d[3])
        : "r"(a0), "r"(a1), "r"(a2), "r"(a3), "r"(b0), "r"(b1));
}

// ---------------- split-precision bf16 projection GEMM ----------------------
// out[b,h,s,d] = (X @ W + bias) * scale, via xh*wh + xh*wl + xl*wh
// BM=128, BN=128, BK=32; 256 threads (8 warps, 2x4); warp tile 64x32.
// smem per stage: 4 matrices (aHi,aLo,bHi,bLo) of [128][PAD=40] bf16.
#define PAD      40                          // halves; row stride 80B (conflict-free LDS)
#define MAT_B    (128 * PAD * 2)             // 10240 bytes per matrix
#define STAGE_B  (4 * MAT_B)                 // 40960 bytes per stage
#define NKCH     (KD_ / 32)                  // 32 chunks

__global__ __launch_bounds__(256) void proj_mma_kernel(
    const __nv_bfloat16* __restrict__ xhi, const __nv_bfloat16* __restrict__ xlo,
    const __nv_bfloat16* __restrict__ whiT, const __nv_bfloat16* __restrict__ wloT,
    const float* __restrict__ bias, float* __restrict__ out, float scale)
{
    extern __shared__ char psm[];

    const int tid  = threadIdx.x;
    const int wid  = tid >> 5;
    const int lane = tid & 31;
    const int wm   = wid >> 2;          // 0..1  (64 m-rows each)
    const int wn   = wid & 3;           // 0..3  (32 n-cols each)
    const int bm   = blockIdx.y * 128;
    const int bn   = blockIdx.x * 128;

    float acc[4][4][4];
    #pragma unroll
    for (int i = 0; i < 4; i++)
        #pragma unroll
        for (int j = 0; j < 4; j++)
            #pragma unroll
            for (int r = 0; r < 4; r++) acc[i][j][r] = 0.f;

    // -------- global load staging: 8 uint4 per thread per chunk ------------
    uint4 v[8];
    auto ldg = [&](int c) {
        const int k0 = c * 32;
        #pragma unroll
        for (int t = 0; t < 8; t++) {
            int idx = tid + t * 256;          // 0..2047
            int mat = idx >> 9;               // 0:aHi 1:aLo 2:bHi 3:bLo
            int rr  = (idx >> 2) & 127;
            int u   = idx & 3;                // 16B unit in 64B row-chunk
            const __nv_bfloat16* src;
            size_t off;
            if (mat < 2) off = (size_t)(bm + rr) * KD_ + k0 + u * 8;
            else         off = (size_t)(bn + rr) * KD_ + k0 + u * 8;
            src = (mat == 0) ? xhi : (mat == 1) ? xlo : (mat == 2) ? whiT : wloT;
            v[t] = *(const uint4*)(src + off);
        }
    };
    auto sts = [&](int s) {
        #pragma unroll
        for (int t = 0; t < 8; t++) {
            int idx = tid + t * 256;
            int mat = idx >> 9;
            int rr  = (idx >> 2) & 127;
            int u   = idx & 3;
            *(uint4*)(psm + s * STAGE_B + mat * MAT_B + rr * (PAD * 2) + u * 16) = v[t];
        }
    };

    // fragment smem byte-address helpers (within one matrix)
    const int fr = lane >> 2;           // 0..7
    const int fc = (lane & 3) * 2;      // 0,2,4,6

    auto compute = [&](int s) {
        const char* aHi = psm + s * STAGE_B;
        const char* aLo = aHi + MAT_B;
        const char* bHi = aHi + 2 * MAT_B;
        const char* bLo = aHi + 3 * MAT_B;
        #pragma unroll
        for (int ks = 0; ks < 2; ks++) {
            const int kc = ks * 16;
            uint32_t af[4][4], bh[4][2], bl[4][2], al[4][4];
            #pragma unroll
            for (int i = 0; i < 4; i++) {
                int r0 = wm * 64 + i * 16 + fr;
                af[i][0] = *(const uint32_t*)(aHi + (r0    ) * (PAD*2) + (kc + fc    ) * 2);
                af[i][1] = *(const uint32_t*)(aHi + (r0 + 8) * (PAD*2) + (kc + fc    ) * 2);
                af[i][2] = *(const uint32_t*)(aHi + (r0    ) * (PAD*2) + (kc + fc + 8) * 2);
                af[i][3] = *(const uint32_t*)(aHi + (r0 + 8) * (PAD*2) + (kc + fc + 8) * 2);
            }
            #pragma unroll
            for (int j = 0; j < 4; j++) {
                int n0 = wn * 32 + j * 8 + fr;
                bh[j][0] = *(const uint32_t*)(bHi + n0 * (PAD*2) + (kc + fc    ) * 2);
                bh[j][1] = *(const uint32_t*)(bHi + n0 * (PAD*2) + (kc + fc + 8) * 2);
            }
            #pragma unroll
            for (int i = 0; i < 4; i++)
                #pragma unroll
                for (int j = 0; j < 4; j++)
                    mma_bf16(acc[i][j], af[i][0], af[i][1], af[i][2], af[i][3],
                             bh[j][0], bh[j][1]);
            #pragma unroll
            for (int j = 0; j < 4; j++) {
                int n0 = wn * 32 + j * 8 + fr;
                bl[j][0] = *(const uint32_t*)(bLo + n0 * (PAD*2) + (kc + fc    ) * 2);
                bl[j][1] = *(const uint32_t*)(bLo + n0 * (PAD*2) + (kc + fc + 8) * 2);
            }
            #pragma unroll
            for (int i = 0; i < 4; i++)
                #pragma unroll
                for (int j = 0; j < 4; j++)
                    mma_bf16(acc[i][j], af[i][0], af[i][1], af[i][2], af[i][3],
                             bl[j][0], bl[j][1]);
            #pragma unroll
            for (int i = 0; i < 4; i++) {
                int r0 = wm * 64 + i * 16 + fr;
                al[i][0] = *(const uint32_t*)(aLo + (r0    ) * (PAD*2) + (kc + fc    ) * 2);
                al[i][1] = *(const uint32_t*)(aLo + (r0 + 8) * (PAD*2) + (kc + fc    ) * 2);
                al[i][2] = *(const uint32_t*)(aLo + (r0    ) * (PAD*2) + (kc + fc + 8) * 2);
                al[i][3] = *(const uint32_t*)(aLo + (r0 + 8) * (PAD*2) + (kc + fc + 8) * 2);
            }
            #pragma unroll
            for (int i = 0; i < 4; i++)
                #pragma unroll
                for (int j = 0; j < 4; j++)
                    mma_bf16(acc[i][j], al[i][0], al[i][1], al[i][2], al[i][3],
                             bh[j][0], bh[j][1]);
        }
    };

    // -------- pipelined main loop ------------------------------------------
    ldg(0);
    int s = 0;
    for (int c = 0; c < NKCH; c++) {
        sts(s);
        __syncthreads();
        if (c + 1 < NKCH) ldg(c + 1);
        compute(s);
        __syncthreads();
        s ^= 1;
    }

    // -------- epilogue: bias + scale, scatter to [B,H,S,64] ----------------
    #pragma unroll
    for (int i = 0; i < 4; i++) {
        #pragma unroll
        for (int rr = 0; rr < 2; rr++) {
            int m = bm + wm * 64 + i * 16 + fr + rr * 8;
            int b = m >> 11;
            int sdx = m & (S_ - 1);
            #pragma unroll
            for (int j = 0; j < 4; j++) {
                int n0 = bn + wn * 32 + j * 8 + fc;
                int h  = n0 >> 6;
                int d  = n0 & 63;
                float2 o;
                o.x = (acc[i][j][rr * 2 + 0] + bias[n0 + 0]) * scale;
                o.y = (acc[i][j][rr * 2 + 1] + bias[n0 + 1]) * scale;
                *(float2*)&out[(((size_t)(b * H_ + h) * S_) + sdx) * DK_ + d] = o;
            }
        }
    }
}

// ---------------------------------------------------------------------------
// Attention (unchanged, known-good): one block per (b,h, 64-query tile).
// ---------------------------------------------------------------------------
__global__ __launch_bounds__(256) void attn_kernel(
    const float* __restrict__ maskg, float* __restrict__ out)
{
    extern __shared__ float sm[];
    float* qT     = sm;
    float* kPT    = sm + 64 * LDS;
    float* Vs     = sm + 2 * 64 * LDS;
    float* mask_s = sm + 3 * 64 * LDS;
    float* denom  = mask_s + 64;

    const int tid = threadIdx.x;
    const int tx  = tid & 15;
    const int ty  = tid >> 4;
    const int bh  = blockIdx.y;
    const int b   = bh >> 4;
    const int h   = bh & 15;
    const int q0  = blockIdx.x * 64;

    const float* qg = g_q + ((size_t)bh * S_ + q0) * DK_;

    #pragma unroll
    for (int it = 0; it < 4; it++) {
        int idx = tid + it * 256;
        int row = idx >> 4;
        int c   = (idx & 15) << 2;
        float4 a = *(const float4*)&qg[row * DK_ + c];
        qT[(c + 0) * LDS + row] = a.x;
        qT[(c + 1) * LDS + row] = a.y;
        qT[(c + 2) * LDS + row] = a.z;
        qT[(c + 3) * LDS + row] = a.w;
    }
    if (tid < 64) denom[tid] = 0.f;

    float o_acc[4][4];
    #pragma unroll
    for (int i = 0; i < 4; i++)
        #pragma unroll
        for (int j = 0; j < 4; j++) o_acc[i][j] = 0.f;

    for (int kt = 0; kt < S_ / 64; kt++) {
        const int k0 = kt * 64;
        const float* kg = g_k + ((size_t)bh * S_ + k0) * DK_;
        const float* vg = g_v + ((size_t)bh * S_ + k0) * DK_;

        __syncthreads();

        #pragma unroll
        for (int it = 0; it < 4; it++) {
            int idx = tid + it * 256;
            int row = idx >> 4;
            int c   = (idx & 15) << 2;
            float4 a = *(const float4*)&kg[row * DK_ + c];
            kPT[(c + 0) * LDS + row] = a.x;
            kPT[(c + 1) * LDS + row] = a.y;
            kPT[(c + 2) * LDS + row] = a.z;
            kPT[(c + 3) * LDS + row] = a.w;
            *(float4*)&Vs[row * LDS + c] = *(const float4*)&vg[row * DK_ + c];
        }
        if (tid < 64) mask_s[tid] = maskg[b * S_ + k0 + tid];
        __syncthreads();

        float sreg[4][4];
        #pragma unroll
        for (int i = 0; i < 4; i++)
            #pragma unroll
            for (int j = 0; j < 4; j++) sreg[i][j] = 0.f;

        #pragma unroll 8
        for (int d = 0; d < 64; d++) {
            float qa[4], ka[4];
            *(float4*)qa = *(float4*)&qT[d * LDS + ty * 4];
            *(float4*)ka = *(float4*)&kPT[d * LDS + tx * 4];
            #pragma unroll
            for (int i = 0; i < 4; i++)
                #pragma unroll
                for (int j = 0; j < 4; j++)
                    sreg[i][j] += qa[i] * ka[j];
        }
        __syncthreads();

        float mk[4];
        #pragma unroll
        for (int j = 0; j < 4; j++) mk[j] = mask_s[tx * 4 + j];

        #pragma unroll
        for (int i = 0; i < 4; i++) {
            float r = 0.f;
            #pragma unroll
            for (int j = 0; j < 4; j++) {
                float p = __expf(sreg[i][j]) * mk[j];
                kPT[(tx * 4 + j) * LDS + ty * 4 + i] = p;
                r += p;
            }
            r += __shfl_xor_sync(0xffffffffu, r, 8);
            r += __shfl_xor_sync(0xffffffffu, r, 4);
            r += __shfl_xor_sync(0xffffffffu, r, 2);
            r += __shfl_xor_sync(0xffffffffu, r, 1);
            if (tx == 0) denom[ty * 4 + i] += r;
        }
        __syncthreads();

        #pragma unroll 8
        for (int kk = 0; kk < 64; kk++) {
            float pa[4], va[4];
            *(float4*)pa = *(float4*)&kPT[kk * LDS + ty * 4];
            *(float4*)va = *(float4*)&Vs[kk * LDS + tx * 4];
            #pragma unroll
            for (int i = 0; i < 4; i++)
                #pragma unroll
                for (int j = 0; j < 4; j++)
                    o_acc[i][j] += pa[i] * va[j];
        }
    }
    __syncthreads();

    #pragma unroll
    for (int i = 0; i < 4; i++) {
        int q = q0 + ty * 4 + i;
        float inv = 1.f / (denom[ty * 4 + i] + 1e-8f);
        float4 o;
        o.x = o_acc[i][0] * inv;
        o.y = o_acc[i][1] * inv;
        o.z = o_acc[i][2] * inv;
        o.w = o_acc[i][3] * inv;
        *(float4*)&out[((size_t)(b * S_ + q)) * N_ + h * DK_ + tx * 4] = o;
    }
}

// ---------------------------------------------------------------------------
extern "C" void kernel_launch(void* const* d_in, const int* in_sizes, int n_in,
                              void* d_out, int out_size)
{
    const float* Q    = (const float*)d_in[0];
    const float* Kin  = (const float*)d_in[1];
    const float* Vin  = (const float*)d_in[2];
    const float* mask = (const float*)d_in[3];
    const float* Wq   = (const float*)d_in[4];
    const float* bq   = (const float*)d_in[5];
    const float* Wk   = (const float*)d_in[6];
    const float* bk   = (const float*)d_in[7];
    const float* Wv   = (const float*)d_in[8];
    const float* bv   = (const float*)d_in[9];
    float* out = (float*)d_out;

    float *dq, *dk, *dv;
    cudaGetSymbolAddress((void**)&dq, g_q);
    cudaGetSymbolAddress((void**)&dk, g_k);
    cudaGetSymbolAddress((void**)&dv, g_v);
    __nv_bfloat16 *xhi, *xlo, *whiT, *wloT;
    cudaGetSymbolAddress((void**)&xhi,  g_xhi);
    cudaGetSymbolAddress((void**)&xlo,  g_xlo);
    cudaGetSymbolAddress((void**)&whiT, g_wThi);
    cudaGetSymbolAddress((void**)&wloT, g_wTlo);

    const int psmem = 2 * STAGE_B;   // 81920 bytes
    cudaFuncSetAttribute(proj_mma_kernel,
                         cudaFuncAttributeMaxDynamicSharedMemorySize, psmem);

    dim3 pg(N_ / 128, M_ / 128);           // (8, 64)
    const int nX = M_ * KD_;
    const int nW = KD_ * N_;

    // Q projection (fold 1/sqrt(DK) into scale)
    split_kernel <<<(nX + 255) / 256, 256>>>(Q, xhi, xlo, nX);
    splitT_kernel<<<(nW + 255) / 256, 256>>>(Wq, whiT, wloT);
    proj_mma_kernel<<<pg, 256, psmem>>>(xhi, xlo, whiT, wloT, bq, dq, 0.125f);
    // K projection
    split_kernel <<<(nX + 255) / 256, 256>>>(Kin, xhi, xlo, nX);
    splitT_kernel<<<(nW + 255) / 256, 256>>>(Wk, whiT, wloT);
    proj_mma_kernel<<<pg, 256, psmem>>>(xhi, xlo, whiT, wloT, bk, dk, 1.0f);
    // V projection
    split_kernel <<<(nX + 255) / 256, 256>>>(Vin, xhi, xlo, nX);
    splitT_kernel<<<(nW + 255) / 256, 256>>>(Wv, whiT, wloT);
    proj_mma_kernel<<<pg, 256, psmem>>>(xhi, xlo, whiT, wloT, bv, dv, 1.0f);

    size_t smem = (size_t)(3 * 64 * LDS + 128) * sizeof(float);
    cudaFuncSetAttribute(attn_kernel,
                         cudaFuncAttributeMaxDynamicSharedMemorySize, (int)smem);
    attn_kernel<<<dim3(S_ / 64, B_ * H_), 256, smem>>>(mask, out);
}

// round 5
// speedup vs baseline: 2.5292x; 2.1352x over previous
#include <cuda_runtime.h>
#include <cuda_bf16.h>
#include <cstdint>

#define B_  4
#define S_  2048
#define D_  1024
#define H_  16
#define DK_ 64
#define M_  (B_*S_)    // 8192
#define N_  (H_*DK_)   // 1024
#define KD_ D_         // 1024

// ---------------- device scratch (allocation-free rule: device globals) ----
__device__ __nv_bfloat16 g_xhi[M_*KD_];
__device__ __nv_bfloat16 g_xlo[M_*KD_];
__device__ __nv_bfloat16 g_wThi[N_*KD_];   // W transposed: [n][k]
__device__ __nv_bfloat16 g_wTlo[N_*KD_];
__device__ __nv_bfloat16 g_qh[B_*H_*S_*DK_];   // [bh][s][64]
__device__ __nv_bfloat16 g_ql[B_*H_*S_*DK_];
__device__ __nv_bfloat16 g_kh[B_*H_*S_*DK_];
__device__ __nv_bfloat16 g_kl[B_*H_*S_*DK_];
__device__ __nv_bfloat16 g_vth[B_*H_*DK_*S_];  // V^T: [bh][d][s]
__device__ __nv_bfloat16 g_vtl[B_*H_*DK_*S_];

// ---------------- helpers ---------------------------------------------------
__device__ __forceinline__ uint32_t smem_u32(const void* p) {
    uint32_t a;
    asm("{ .reg .u64 t; cvta.to.shared.u64 t, %1; cvt.u32.u64 %0, t; }"
        : "=r"(a) : "l"(p));
    return a;
}
__device__ __forceinline__ void cp16(void* dst, const void* src) {
    asm volatile("cp.async.cg.shared.global [%0], [%1], 16;"
                 :: "r"(smem_u32(dst)), "l"(src));
}
#define CP_COMMIT() asm volatile("cp.async.commit_group;" ::: "memory")
#define CP_WAIT1()  asm volatile("cp.async.wait_group 1;" ::: "memory")
#define CP_WAIT0()  asm volatile("cp.async.wait_group 0;" ::: "memory")

__device__ __forceinline__ void mma_bf16(float* d,
                                         uint32_t a0, uint32_t a1, uint32_t a2, uint32_t a3,
                                         uint32_t b0, uint32_t b1)
{
    asm volatile(
        "mma.sync.aligned.m16n8k16.row.col.f32.bf16.bf16.f32 "
        "{%0,%1,%2,%3}, {%4,%5,%6,%7}, {%8,%9}, {%0,%1,%2,%3};"
        : "+f"(d[0]), "+f"(d[1]), "+f"(d[2]), "+f"(d[3])
        : "r"(a0), "r"(a1), "r"(a2), "r"(a3), "r"(b0), "r"(b1));
}
__device__ __forceinline__ uint32_t pack_bf16x2(float lo, float hi) {
    uint32_t r;
    asm("cvt.rn.bf16x2.f32 %0, %1, %2;" : "=r"(r) : "f"(hi), "f"(lo));
    return r;
}

// ---------------- fp32 -> bf16 hi/lo split kernels --------------------------
__global__ void split_kernel(const float* __restrict__ x,
                             __nv_bfloat16* __restrict__ hi,
                             __nv_bfloat16* __restrict__ lo, int n)
{
    int i = blockIdx.x * blockDim.x + threadIdx.x;
    if (i < n) {
        float v = x[i];
        __nv_bfloat16 h = __float2bfloat16(v);
        hi[i] = h;
        lo[i] = __float2bfloat16(v - __bfloat162float(h));
    }
}
__global__ void splitT_kernel(const float* __restrict__ w,
                              __nv_bfloat16* __restrict__ hiT,
                              __nv_bfloat16* __restrict__ loT)
{
    int idx = blockIdx.x * blockDim.x + threadIdx.x;   // = n*1024 + k
    if (idx < N_ * KD_) {
        int n = idx >> 10, k = idx & 1023;
        float v = w[k * N_ + n];
        __nv_bfloat16 h = __float2bfloat16(v);
        hiT[idx] = h;
        loT[idx] = __float2bfloat16(v - __bfloat162float(h));
    }
}

// ---------------- split-precision bf16 projection GEMM ----------------------
// BM=128, BN=128, BK=32; 256 threads; warp tile 64x32.
// vmode=0: out hi/lo [bh][s][64]; vmode=1: out hi/lo transposed [bh][d][S]
#define PAD      40
#define MAT_B    (128 * PAD * 2)
#define STAGE_B  (4 * MAT_B)
#define NKCH     (KD_ / 32)

__global__ __launch_bounds__(256) void proj_mma_kernel(
    const __nv_bfloat16* __restrict__ xhi, const __nv_bfloat16* __restrict__ xlo,
    const __nv_bfloat16* __restrict__ whiT, const __nv_bfloat16* __restrict__ wloT,
    const float* __restrict__ bias,
    __nv_bfloat16* __restrict__ outh, __nv_bfloat16* __restrict__ outl,
    float scale, int vmode)
{
    extern __shared__ char psm[];

    const int tid  = threadIdx.x;
    const int wid  = tid >> 5;
    const int lane = tid & 31;
    const int wm   = wid >> 2;
    const int wn   = wid & 3;
    const int bm   = blockIdx.y * 128;
    const int bn   = blockIdx.x * 128;

    float acc[4][4][4];
    #pragma unroll
    for (int i = 0; i < 4; i++)
        #pragma unroll
        for (int j = 0; j < 4; j++)
            #pragma unroll
            for (int r = 0; r < 4; r++) acc[i][j][r] = 0.f;

    uint4 v[8];
    auto ldg = [&](int c) {
        const int k0 = c * 32;
        #pragma unroll
        for (int t = 0; t < 8; t++) {
            int idx = tid + t * 256;
            int mat = idx >> 9;
            int rr  = (idx >> 2) & 127;
            int u   = idx & 3;
            const __nv_bfloat16* src;
            size_t off;
            if (mat < 2) off = (size_t)(bm + rr) * KD_ + k0 + u * 8;
            else         off = (size_t)(bn + rr) * KD_ + k0 + u * 8;
            src = (mat == 0) ? xhi : (mat == 1) ? xlo : (mat == 2) ? whiT : wloT;
            v[t] = *(const uint4*)(src + off);
        }
    };
    auto sts = [&](int s) {
        #pragma unroll
        for (int t = 0; t < 8; t++) {
            int idx = tid + t * 256;
            int mat = idx >> 9;
            int rr  = (idx >> 2) & 127;
            int u   = idx & 3;
            *(uint4*)(psm + s * STAGE_B + mat * MAT_B + rr * (PAD * 2) + u * 16) = v[t];
        }
    };

    const int fr = lane >> 2;
    const int fc = (lane & 3) * 2;

    auto compute = [&](int s) {
        const char* aHi = psm + s * STAGE_B;
        const char* aLo = aHi + MAT_B;
        const char* bHi = aHi + 2 * MAT_B;
        const char* bLo = aHi + 3 * MAT_B;
        #pragma unroll
        for (int ks = 0; ks < 2; ks++) {
            const int kc = ks * 16;
            uint32_t af[4][4], bh[4][2], bl[4][2], al[4][4];
            #pragma unroll
            for (int i = 0; i < 4; i++) {
                int r0 = wm * 64 + i * 16 + fr;
                af[i][0] = *(const uint32_t*)(aHi + (r0    ) * (PAD*2) + (kc + fc    ) * 2);
                af[i][1] = *(const uint32_t*)(aHi + (r0 + 8) * (PAD*2) + (kc + fc    ) * 2);
                af[i][2] = *(const uint32_t*)(aHi + (r0    ) * (PAD*2) + (kc + fc + 8) * 2);
                af[i][3] = *(const uint32_t*)(aHi + (r0 + 8) * (PAD*2) + (kc + fc + 8) * 2);
            }
            #pragma unroll
            for (int j = 0; j < 4; j++) {
                int n0 = wn * 32 + j * 8 + fr;
                bh[j][0] = *(const uint32_t*)(bHi + n0 * (PAD*2) + (kc + fc    ) * 2);
                bh[j][1] = *(const uint32_t*)(bHi + n0 * (PAD*2) + (kc + fc + 8) * 2);
            }
            #pragma unroll
            for (int i = 0; i < 4; i++)
                #pragma unroll
                for (int j = 0; j < 4; j++)
                    mma_bf16(acc[i][j], af[i][0], af[i][1], af[i][2], af[i][3],
                             bh[j][0], bh[j][1]);
            #pragma unroll
            for (int j = 0; j < 4; j++) {
                int n0 = wn * 32 + j * 8 + fr;
                bl[j][0] = *(const uint32_t*)(bLo + n0 * (PAD*2) + (kc + fc    ) * 2);
                bl[j][1] = *(const uint32_t*)(bLo + n0 * (PAD*2) + (kc + fc + 8) * 2);
            }
            #pragma unroll
            for (int i = 0; i < 4; i++)
                #pragma unroll
                for (int j = 0; j < 4; j++)
                    mma_bf16(acc[i][j], af[i][0], af[i][1], af[i][2], af[i][3],
                             bl[j][0], bl[j][1]);
            #pragma unroll
            for (int i = 0; i < 4; i++) {
                int r0 = wm * 64 + i * 16 + fr;
                al[i][0] = *(const uint32_t*)(aLo + (r0    ) * (PAD*2) + (kc + fc    ) * 2);
                al[i][1] = *(const uint32_t*)(aLo + (r0 + 8) * (PAD*2) + (kc + fc    ) * 2);
                al[i][2] = *(const uint32_t*)(aLo + (r0    ) * (PAD*2) + (kc + fc + 8) * 2);
                al[i][3] = *(const uint32_t*)(aLo + (r0 + 8) * (PAD*2) + (kc + fc + 8) * 2);
            }
            #pragma unroll
            for (int i = 0; i < 4; i++)
                #pragma unroll
                for (int j = 0; j < 4; j++)
                    mma_bf16(acc[i][j], al[i][0], al[i][1], al[i][2], al[i][3],
                             bh[j][0], bh[j][1]);
        }
    };

    ldg(0);
    int s = 0;
    for (int c = 0; c < NKCH; c++) {
        sts(s);
        __syncthreads();
        if (c + 1 < NKCH) ldg(c + 1);
        compute(s);
        __syncthreads();
        s ^= 1;
    }

    // epilogue: bias+scale, split to hi/lo, write (optionally V-transposed)
    #pragma unroll
    for (int i = 0; i < 4; i++) {
        #pragma unroll
        for (int rr = 0; rr < 2; rr++) {
            int m = bm + wm * 64 + i * 16 + fr + rr * 8;
            int b = m >> 11;
            int sdx = m & (S_ - 1);
            #pragma unroll
            for (int j = 0; j < 4; j++) {
                int n0 = bn + wn * 32 + j * 8 + fc;
                int h  = n0 >> 6;
                int d  = n0 & 63;
                float x0 = (acc[i][j][rr * 2 + 0] + bias[n0 + 0]) * scale;
                float x1 = (acc[i][j][rr * 2 + 1] + bias[n0 + 1]) * scale;
                __nv_bfloat16 h0 = __float2bfloat16(x0);
                __nv_bfloat16 h1 = __float2bfloat16(x1);
                __nv_bfloat16 l0 = __float2bfloat16(x0 - __bfloat162float(h0));
                __nv_bfloat16 l1 = __float2bfloat16(x1 - __bfloat162float(h1));
                if (!vmode) {
                    size_t o = (((size_t)(b * H_ + h) * S_) + sdx) * DK_ + d;
                    __nv_bfloat162 ph; ph.x = h0; ph.y = h1;
                    __nv_bfloat162 pl; pl.x = l0; pl.y = l1;
                    *(__nv_bfloat162*)&outh[o] = ph;
                    *(__nv_bfloat162*)&outl[o] = pl;
                } else {
                    size_t o = ((size_t)(b * H_ + h) * DK_ + d) * S_ + sdx;
                    outh[o] = h0; outh[o + S_] = h1;
                    outl[o] = l0; outl[o + S_] = l1;
                }
            }
        }
    }
}

// ---------------- tensor-core attention -------------------------------------
// Block: (b,h, 128-q tile); 8 warps x 16 q-rows; stream 64-key chunks.
#define BR   128
#define KC   64
#define NCHA (S_ / KC)     // 32
#define QSTR 144           // bytes/row (72 bf16)
#define KMAT (64 * QSTR)   // 9216
#define STG  (4 * KMAT + 256)
#define OFFK (2 * 128 * QSTR)   // 36864 (after qh, ql)

__global__ __launch_bounds__(256, 1) void attn_mma_kernel(
    const float* __restrict__ maskg, float* __restrict__ out)
{
    extern __shared__ char smc[];

    const int tid  = threadIdx.x;
    const int wid  = tid >> 5;
    const int lane = tid & 31;
    const int fr   = lane >> 2;
    const int fc   = (lane & 3) * 2;
    const int bh   = blockIdx.y;
    const int b    = bh >> 4;
    const int h    = bh & 15;
    const int bm   = blockIdx.x * BR;
    const int wq0  = wid * 16;

    const __nv_bfloat16* qh_g = g_qh + ((size_t)bh * S_ + bm) * DK_;
    const __nv_bfloat16* ql_g = g_ql + ((size_t)bh * S_ + bm) * DK_;

    // ---- Q loads (cp.async): 2 matrices x 1024 16B units (128 rows x 8 units)
    #pragma unroll
    for (int t = 0; t < 4; t++) {
        int idx = tid + t * 256;          // 0..1023
        int r = idx >> 3, u = idx & 7;
        cp16(smc + r * QSTR + u * 16,              qh_g + r * DK_ + u * 8);
        cp16(smc + 128 * QSTR + r * QSTR + u * 16, ql_g + r * DK_ + u * 8);
    }

    auto load_chunk = [&](int c, int s) {
        const int k0 = c * KC;
        char* st = smc + OFFK + s * STG;
        #pragma unroll
        for (int t = 0; t < 2; t++) {
            int idx = tid + t * 256;      // 0..511 : 64 rows x 8 units
            int r = idx >> 3, u = idx & 7;
            cp16(st + r * QSTR + u * 16,
                 g_kh + ((size_t)bh * S_ + k0 + r) * DK_ + u * 8);
            cp16(st + KMAT + r * QSTR + u * 16,
                 g_kl + ((size_t)bh * S_ + k0 + r) * DK_ + u * 8);
            cp16(st + 2 * KMAT + r * QSTR + u * 16,
                 g_vth + ((size_t)bh * DK_ + r) * S_ + k0 + u * 8);
            cp16(st + 3 * KMAT + r * QSTR + u * 16,
                 g_vtl + ((size_t)bh * DK_ + r) * S_ + k0 + u * 8);
        }
        if (tid < 16) cp16(st + 4 * KMAT + tid * 16, maskg + (size_t)b * S_ + k0 + tid * 4);
        CP_COMMIT();
    };

    load_chunk(0, 0);

    uint32_t qf[4][4], qlf[4][4];
    float accO[8][4];
    #pragma unroll
    for (int n = 0; n < 8; n++)
        #pragma unroll
        for (int r = 0; r < 4; r++) accO[n][r] = 0.f;
    float den0 = 0.f, den1 = 0.f;

    for (int c = 0; c < NCHA; c++) {
        const int s = c & 1;
        if (c + 1 < NCHA) load_chunk(c + 1, s ^ 1);
        if (c + 1 < NCHA) { CP_WAIT1(); } else { CP_WAIT0(); }
        __syncthreads();

        if (c == 0) {
            // Q register fragments (once)
            const char* qhB = smc;
            const char* qlB = smc + 128 * QSTR;
            int r0 = wq0 + fr;
            #pragma unroll
            for (int kt = 0; kt < 4; kt++) {
                int cb = (kt * 16 + fc) * 2;
                qf[kt][0]  = *(const uint32_t*)(qhB + r0 * QSTR + cb);
                qf[kt][1]  = *(const uint32_t*)(qhB + (r0 + 8) * QSTR + cb);
                qf[kt][2]  = *(const uint32_t*)(qhB + r0 * QSTR + cb + 16);
                qf[kt][3]  = *(const uint32_t*)(qhB + (r0 + 8) * QSTR + cb + 16);
                qlf[kt][0] = *(const uint32_t*)(qlB + r0 * QSTR + cb);
                qlf[kt][1] = *(const uint32_t*)(qlB + (r0 + 8) * QSTR + cb);
                qlf[kt][2] = *(const uint32_t*)(qlB + r0 * QSTR + cb + 16);
                qlf[kt][3] = *(const uint32_t*)(qlB + (r0 + 8) * QSTR + cb + 16);
            }
        }

        const char* kh = smc + OFFK + s * STG;
        const char* kl = kh + KMAT;
        const char* vh = kh + 2 * KMAT;
        const char* vl = kh + 3 * KMAT;
        const float* mk = (const float*)(kh + 4 * KMAT);

        // ---- scores: 8 n-tiles (64 keys)
        float accs[8][4];
        #pragma unroll
        for (int n = 0; n < 8; n++)
            #pragma unroll
            for (int r = 0; r < 4; r++) accs[n][r] = 0.f;

        #pragma unroll
        for (int kt = 0; kt < 4; kt++) {
            #pragma unroll
            for (int nt = 0; nt < 8; nt++) {
                int nb = (nt * 8 + fr) * QSTR + (kt * 16 + fc) * 2;
                uint32_t bh0 = *(const uint32_t*)(kh + nb);
                uint32_t bh1 = *(const uint32_t*)(kh + nb + 16);
                uint32_t bl0 = *(const uint32_t*)(kl + nb);
                uint32_t bl1 = *(const uint32_t*)(kl + nb + 16);
                mma_bf16(accs[nt], qf[kt][0], qf[kt][1], qf[kt][2], qf[kt][3], bh0, bh1);
                mma_bf16(accs[nt], qf[kt][0], qf[kt][1], qf[kt][2], qf[kt][3], bl0, bl1);
                mma_bf16(accs[nt], qlf[kt][0], qlf[kt][1], qlf[kt][2], qlf[kt][3], bh0, bh1);
            }
        }

        // ---- P = exp(s) * mask; split hi/lo; denom accumulate
        uint32_t phf[4][4], plf[4][4];
        #pragma unroll
        for (int nt = 0; nt < 8; nt++) {
            float m0 = mk[nt * 8 + fc];
            float m1 = mk[nt * 8 + fc + 1];
            #pragma unroll
            for (int rr = 0; rr < 2; rr++) {
                float p0 = __expf(accs[nt][rr * 2 + 0]) * m0;
                float p1 = __expf(accs[nt][rr * 2 + 1]) * m1;
                if (rr == 0) den0 += p0 + p1; else den1 += p0 + p1;
                __nv_bfloat16 b0 = __float2bfloat16(p0);
                __nv_bfloat16 b1 = __float2bfloat16(p1);
                float l0 = p0 - __bfloat162float(b0);
                float l1 = p1 - __bfloat162float(b1);
                phf[nt >> 1][(nt & 1) * 2 + rr] = pack_bf16x2(p0, p1);
                plf[nt >> 1][(nt & 1) * 2 + rr] = pack_bf16x2(l0, l1);
            }
        }

        // ---- O += P @ V  (B = V^T rows = dv)
        #pragma unroll
        for (int kt = 0; kt < 4; kt++) {
            #pragma unroll
            for (int nt = 0; nt < 8; nt++) {
                int nb = (nt * 8 + fr) * QSTR + (kt * 16 + fc) * 2;
                uint32_t vh0 = *(const uint32_t*)(vh + nb);
                uint32_t vh1 = *(const uint32_t*)(vh + nb + 16);
                uint32_t vl0 = *(const uint32_t*)(vl + nb);
                uint32_t vl1 = *(const uint32_t*)(vl + nb + 16);
                mma_bf16(accO[nt], phf[kt][0], phf[kt][1], phf[kt][2], phf[kt][3], vh0, vh1);
                mma_bf16(accO[nt], phf[kt][0], phf[kt][1], phf[kt][2], phf[kt][3], vl0, vl1);
                mma_bf16(accO[nt], plf[kt][0], plf[kt][1], plf[kt][2], plf[kt][3], vh0, vh1);
            }
        }
        __syncthreads();
    }

    // ---- denom reduce across quad, divide, store
    den0 += __shfl_xor_sync(0xffffffffu, den0, 1);
    den0 += __shfl_xor_sync(0xffffffffu, den0, 2);
    den1 += __shfl_xor_sync(0xffffffffu, den1, 1);
    den1 += __shfl_xor_sync(0xffffffffu, den1, 2);
    float inv0 = 1.f / (den0 + 1e-8f);
    float inv1 = 1.f / (den1 + 1e-8f);

    int q = bm + wq0 + fr;
    #pragma unroll
    for (int nt = 0; nt < 8; nt++) {
        int col = h * DK_ + nt * 8 + fc;
        float2 o0; o0.x = accO[nt][0] * inv0; o0.y = accO[nt][1] * inv0;
        float2 o1; o1.x = accO[nt][2] * inv1; o1.y = accO[nt][3] * inv1;
        *(float2*)&out[((size_t)(b * S_ + q)) * N_ + col] = o0;
        *(float2*)&out[((size_t)(b * S_ + q + 8)) * N_ + col] = o1;
    }
}

// ---------------------------------------------------------------------------
extern "C" void kernel_launch(void* const* d_in, const int* in_sizes, int n_in,
                              void* d_out, int out_size)
{
    const float* Q    = (const float*)d_in[0];
    const float* Kin  = (const float*)d_in[1];
    const float* Vin  = (const float*)d_in[2];
    const float* mask = (const float*)d_in[3];
    const float* Wq   = (const float*)d_in[4];
    const float* bq   = (const float*)d_in[5];
    const float* Wk   = (const float*)d_in[6];
    const float* bk   = (const float*)d_in[7];
    const float* Wv   = (const float*)d_in[8];
    const float* bv   = (const float*)d_in[9];
    float* out = (float*)d_out;

    __nv_bfloat16 *xhi, *xlo, *whiT, *wloT;
    __nv_bfloat16 *qh, *ql, *kh, *kl, *vth, *vtl;
    cudaGetSymbolAddress((void**)&xhi,  g_xhi);
    cudaGetSymbolAddress((void**)&xlo,  g_xlo);
    cudaGetSymbolAddress((void**)&whiT, g_wThi);
    cudaGetSymbolAddress((void**)&wloT, g_wTlo);
    cudaGetSymbolAddress((void**)&qh,  g_qh);
    cudaGetSymbolAddress((void**)&ql,  g_ql);
    cudaGetSymbolAddress((void**)&kh,  g_kh);
    cudaGetSymbolAddress((void**)&kl,  g_kl);
    cudaGetSymbolAddress((void**)&vth, g_vth);
    cudaGetSymbolAddress((void**)&vtl, g_vtl);

    const int psmem = 2 * STAGE_B;   // 81920
    cudaFuncSetAttribute(proj_mma_kernel,
                         cudaFuncAttributeMaxDynamicSharedMemorySize, psmem);

    dim3 pg(N_ / 128, M_ / 128);
    const int nX = M_ * KD_;
    const int nW = KD_ * N_;

    split_kernel <<<(nX + 255) / 256, 256>>>(Q, xhi, xlo, nX);
    splitT_kernel<<<(nW + 255) / 256, 256>>>(Wq, whiT, wloT);
    proj_mma_kernel<<<pg, 256, psmem>>>(xhi, xlo, whiT, wloT, bq, qh, ql, 0.125f, 0);

    split_kernel <<<(nX + 255) / 256, 256>>>(Kin, xhi, xlo, nX);
    splitT_kernel<<<(nW + 255) / 256, 256>>>(Wk, whiT, wloT);
    proj_mma_kernel<<<pg, 256, psmem>>>(xhi, xlo, whiT, wloT, bk, kh, kl, 1.0f, 0);

    split_kernel <<<(nX + 255) / 256, 256>>>(Vin, xhi, xlo, nX);
    splitT_kernel<<<(nW + 255) / 256, 256>>>(Wv, whiT, wloT);
    proj_mma_kernel<<<pg, 256, psmem>>>(xhi, xlo, whiT, wloT, bv, vth, vtl, 1.0f, 1);

    const int asmem = OFFK + 2 * STG;   // 36864 + 74240 = 111104
    cudaFuncSetAttribute(attn_mma_kernel,
                         cudaFuncAttributeMaxDynamicSharedMemorySize, asmem);
    attn_mma_kernel<<<dim3(S_ / BR, B_ * H_), 256, asmem>>>(mask, out);
}